// round 12
// baseline (speedup 1.0000x reference)
#include <cuda_runtime.h>
#include <cstdint>

#define M_TOTAL 16384
#define K_DIM   2048
#define E_DIM   64
#define TOPK    8

#define BM    128
#define BK    128
#define NTILE (K_DIM / BK)   // 16
#define NTHR  256
#define LSTR  68             // epilogue logits row stride (floats)
#define ASTR  129            // a_sm row stride: BM + 1 pad -> conflict-free STS/LDS
#define BUFSZ (BK * ASTR + BK * E_DIM)   // 24704 floats per buffer

// One-time W transpose scratch: Wt[k][e]
__device__ float Wt_g[(size_t)K_DIM * E_DIM];

__global__ void transpose_w(const float* __restrict__ W, float* __restrict__ Wt) {
    int t = blockIdx.x * blockDim.x + threadIdx.x;   // 131072
    int e = t >> 11;
    int k = t & (K_DIM - 1);
    Wt[(size_t)k * E_DIM + e] = W[(size_t)e * K_DIM + k];
}

// Packed fp32x2 FMA; per-lane rounding identical to scalar fmaf.
__device__ __forceinline__ float2 ffma2(float2 a, float2 b, float2 c) {
    float2 d;
    asm("fma.rn.f32x2 %0, %1, %2, %3;"
        : "=l"(reinterpret_cast<unsigned long long&>(d))
        : "l"(reinterpret_cast<unsigned long long&>(a)),
          "l"(reinterpret_cast<unsigned long long&>(b)),
          "l"(reinterpret_cast<unsigned long long&>(c)));
    return d;
}

__device__ __forceinline__ void cp_async16(uint32_t dst_smem, const void* src) {
    asm volatile("cp.async.ca.shared.global [%0], [%1], 16;"
                 :: "r"(dst_smem), "l"(src));
}
__device__ __forceinline__ void cp_async_commit() {
    asm volatile("cp.async.commit_group;");
}
__device__ __forceinline__ void cp_async_wait0() {
    asm volatile("cp.async.wait_group 0;");
}

// Fused logits GEMM + top-8 + softmax. BK=128 (16 tiles, 192 KB double
// buffer): minimal per-tile overhead. Warp = 16 experts x 2 m-rows; uniform
// LDS.128 b, coalesced LDS.32 a. a-staging: thread owns m-column tid&127,
// rows q = (tid>>7)+2i -> STS lanes consecutive m = conflict-free; pad
// ASTR=129 keeps mainloop LDS conflict-free with NO swizzle ALU.
// Sequential ascending-k FMA chain per (m,e) -> bit-identical outputs.
__global__ __launch_bounds__(NTHR, 1)
void router_fused(const float* __restrict__ X, const float* __restrict__ Wt,
                  float* __restrict__ logits,
                  float* __restrict__ wout, float* __restrict__ eout) {
    extern __shared__ float smem[];            // 2 * BUFSZ floats

    const int tid  = threadIdx.x;
    const int w    = tid >> 5;
    const int lane = tid & 31;
    const int e0   = (w & 3) * 16;
    const int m1   = (w >> 2) * 64 + lane;
    const int m2   = m1 + 32;
    const int m0   = blockIdx.x * BM;

    const uint32_t smem_u32 = (uint32_t)__cvta_generic_to_shared(smem);

    float2 acc[2][8];
    #pragma unroll
    for (int r = 0; r < 2; r++)
        #pragma unroll
        for (int j = 0; j < 8; j++) acc[r][j] = make_float2(0.f, 0.f);

    // a staging: this thread owns column am (one m-row), float4-rows
    // q = qbase + 2*i (i = 0..15), i.e. k-groups of 4.
    const int am    = tid & 127;
    const int qbase = tid >> 7;            // 0 or 1
    const float* xrow = &X[(size_t)(m0 + am) * K_DIM];

    float4 pa[4];

    // ---- preload tile 0 ----
    {
        // b tile: 2048 float4 -> 8 cp.async per thread
        uint32_t b0 = smem_u32 + (uint32_t)(BK * ASTR) * 4u;
        #pragma unroll
        for (int i = 0; i < 8; i++)
            cp_async16(b0 + (tid + i * NTHR) * 16u, &Wt[(size_t)(tid + i * NTHR) * 4]);
        cp_async_commit();
        // a tile: 16 LDG.128 -> 64 STS.32 (conflict-free)
        #pragma unroll
        for (int i = 0; i < 16; i++) {
            int q = qbase + 2 * i;
            float4 v = *reinterpret_cast<const float4*>(&xrow[q * 4]);
            float vs[4] = {v.x, v.y, v.z, v.w};
            #pragma unroll
            for (int j = 0; j < 4; j++)
                smem[(4 * q + j) * ASTR + am] = vs[j];
        }
        cp_async_wait0();
    }
    __syncthreads();

    for (int t = 0; t < NTILE; t++) {
        const int cur = t & 1;
        const float* a_sm = smem + cur * BUFSZ;
        const float* b_sm = a_sm + BK * ASTR;
        float* a_nx = smem + (cur ^ 1) * BUFSZ;

        const bool has_next = (t + 1 < NTILE);
        const int kn = (t + 1) * BK;

        // issue next-tile b (cp.async) + a batch 0 (LDG)
        if (has_next) {
            uint32_t bdst = smem_u32 + (uint32_t)((cur ^ 1) * BUFSZ + BK * ASTR) * 4u;
            const float* bsrc = &Wt[(size_t)kn * E_DIM];
            #pragma unroll
            for (int i = 0; i < 8; i++)
                cp_async16(bdst + (tid + i * NTHR) * 16u, bsrc + (size_t)(tid + i * NTHR) * 4);
            cp_async_commit();
            #pragma unroll
            for (int i = 0; i < 4; i++)
                pa[i] = *reinterpret_cast<const float4*>(&xrow[kn + (qbase + 2 * i) * 4]);
        }

        // ---- 4 quarter-loops of 32 kk, a-staging between quarters ----
        #pragma unroll 1
        for (int qt = 0; qt < 4; qt++) {
            const int k0 = qt * 32;
            #pragma unroll 8
            for (int kk = k0; kk < k0 + 32; kk++) {
                float4 b4[4];
                #pragma unroll
                for (int j = 0; j < 4; j++)
                    b4[j] = *reinterpret_cast<const float4*>(&b_sm[kk * E_DIM + e0 + 4 * j]);
                float a1 = a_sm[kk * ASTR + m1];
                float a2 = a_sm[kk * ASTR + m2];
                float2 ap1 = make_float2(a1, a1);
                float2 ap2 = make_float2(a2, a2);
                #pragma unroll
                for (int j = 0; j < 4; j++) {
                    float2 blo = make_float2(b4[j].x, b4[j].y);
                    float2 bhi = make_float2(b4[j].z, b4[j].w);
                    acc[0][2 * j]     = ffma2(ap1, blo, acc[0][2 * j]);
                    acc[0][2 * j + 1] = ffma2(ap1, bhi, acc[0][2 * j + 1]);
                    acc[1][2 * j]     = ffma2(ap2, blo, acc[1][2 * j]);
                    acc[1][2 * j + 1] = ffma2(ap2, bhi, acc[1][2 * j + 1]);
                }
            }
            // stage a batch qt, issue next batch
            if (has_next) {
                #pragma unroll
                for (int i = 0; i < 4; i++) {
                    int q = qbase + 2 * (qt * 4 + i);
                    float vs[4] = {pa[i].x, pa[i].y, pa[i].z, pa[i].w};
                    #pragma unroll
                    for (int j = 0; j < 4; j++)
                        a_nx[(4 * q + j) * ASTR + am] = vs[j];
                }
                if (qt < 3) {
                    #pragma unroll
                    for (int i = 0; i < 4; i++) {
                        int q = qbase + 2 * ((qt + 1) * 4 + i);
                        pa[i] = *reinterpret_cast<const float4*>(&xrow[kn + q * 4]);
                    }
                }
            }
        }

        if (has_next) cp_async_wait0();
        __syncthreads();
    }

    // ---- epilogue: logits to global + stage rows in smem for topk ----
    #pragma unroll
    for (int r = 0; r < 2; r++) {
        int m = r ? m2 : m1;
        #pragma unroll
        for (int j = 0; j < 4; j++) {
            float4 v = make_float4(acc[r][2 * j].x, acc[r][2 * j].y,
                                   acc[r][2 * j + 1].x, acc[r][2 * j + 1].y);
            *reinterpret_cast<float4*>(&logits[(size_t)(m0 + m) * E_DIM + e0 + 4 * j]) = v;
            *reinterpret_cast<float4*>(&smem[m * LSTR + e0 + 4 * j]) = v;
        }
    }
    __syncthreads();

    // ---- top-8 + softmax: one thread per token (threads 0..127) ----
    if (tid < BM) {
        const float* row = &smem[tid * LSTR];
        float tv[TOPK];
        int   ti[TOPK];
        #pragma unroll
        for (int i = 0; i < TOPK; i++) { tv[i] = -3.4e38f; ti[i] = 0; }

        #pragma unroll
        for (int q = 0; q < E_DIM / 4; q++) {
            float4 v4 = *reinterpret_cast<const float4*>(&row[q * 4]);
            float vs[4] = {v4.x, v4.y, v4.z, v4.w};
            #pragma unroll
            for (int u = 0; u < 4; u++) {
                float v = vs[u];
                int   e = q * 4 + u;
                if (v > tv[TOPK - 1]) {
                    tv[TOPK - 1] = v; ti[TOPK - 1] = e;
                    #pragma unroll
                    for (int j = TOPK - 1; j > 0; j--) {
                        if (tv[j] > tv[j - 1]) {   // strict: ties keep earlier index
                            float tf = tv[j]; tv[j] = tv[j - 1]; tv[j - 1] = tf;
                            int   tx = ti[j]; ti[j] = ti[j - 1]; ti[j - 1] = tx;
                        }
                    }
                }
            }
        }

        float mx = tv[0];
        float ev[TOPK], ssum = 0.f;
        #pragma unroll
        for (int i = 0; i < TOPK; i++) { ev[i] = __expf(tv[i] - mx); ssum += ev[i]; }
        float inv = 1.f / ssum;
        size_t tok = (size_t)(m0 + tid);
        #pragma unroll
        for (int i = 0; i < TOPK; i++) {
            wout[tok * TOPK + i] = ev[i] * inv;
            eout[tok * TOPK + i] = (float)ti[i];
        }
    }
}

extern "C" void kernel_launch(void* const* d_in, const int* in_sizes, int n_in,
                              void* d_out, int out_size) {
    const float* X = (const float*)d_in[0];   // [4,4096,2048] fp32
    const float* W = (const float*)d_in[1];   // [64,2048]     fp32

    float* out    = (float*)d_out;
    float* logits = out;                                   // 16384*64
    float* wts    = out + (size_t)M_TOTAL * E_DIM;         // 16384*8
    float* exps   = wts + (size_t)M_TOTAL * TOPK;          // 16384*8

    float* Wt;
    cudaGetSymbolAddress((void**)&Wt, Wt_g);

    const int smem_bytes = 2 * BUFSZ * (int)sizeof(float);   // 197632 B
    cudaFuncSetAttribute(router_fused, cudaFuncAttributeMaxDynamicSharedMemorySize,
                         smem_bytes);

    transpose_w<<<(K_DIM * E_DIM) / 256, 256>>>(W, Wt);
    router_fused<<<M_TOTAL / BM, NTHR, smem_bytes>>>(X, Wt, logits, wts, exps);
}

// round 13
// speedup vs baseline: 1.2694x; 1.2694x over previous
#include <cuda_runtime.h>
#include <cstdint>

#define M_TOTAL 16384
#define K_DIM   2048
#define E_DIM   64
#define TOPK    8

#define BM    128
#define BK    128
#define NTILE (K_DIM / BK)   // 16
#define NTHR  256
#define LSTR  68             // epilogue logits row stride (floats)
#define BUFSZ (BK * BM + BK * E_DIM)   // 24576 floats per buffer (96 KB)

// One-time W transpose scratch: Wt[k][e]
__device__ float Wt_g[(size_t)K_DIM * E_DIM];

__global__ void transpose_w(const float* __restrict__ W, float* __restrict__ Wt) {
    int t = blockIdx.x * blockDim.x + threadIdx.x;   // 131072
    int e = t >> 11;
    int k = t & (K_DIM - 1);
    Wt[(size_t)k * E_DIM + e] = W[(size_t)e * K_DIM + k];
}

// Packed fp32x2 FMA; per-lane rounding identical to scalar fmaf.
__device__ __forceinline__ float2 ffma2(float2 a, float2 b, float2 c) {
    float2 d;
    asm("fma.rn.f32x2 %0, %1, %2, %3;"
        : "=l"(reinterpret_cast<unsigned long long&>(d))
        : "l"(reinterpret_cast<unsigned long long&>(a)),
          "l"(reinterpret_cast<unsigned long long&>(b)),
          "l"(reinterpret_cast<unsigned long long&>(c)));
    return d;
}

__device__ __forceinline__ void cp_async16(uint32_t dst_smem, const void* src) {
    asm volatile("cp.async.ca.shared.global [%0], [%1], 16;"
                 :: "r"(dst_smem), "l"(src));
}
__device__ __forceinline__ void cp_async_commit() {
    asm volatile("cp.async.commit_group;");
}
__device__ __forceinline__ void cp_async_wait0() {
    asm volatile("cp.async.wait_group 0;");
}

// Fused logits GEMM + top-8 + softmax. BK=128 (16 tiles, 192 KB double
// buffer) with COALESCED a-staging LDG (warp = one X row, lanes consecutive
// float4 — round 12's regression was uncoalesced staging) and a fully
// conflict-free swizzle col = m ^ (k>>2) (STS banks = row^lane all distinct;
// LDS banks = consecutive m XOR const). Warp = 16 experts x 2 m-rows,
// uniform LDS.128 b. Sequential ascending-k FMA chain per (m,e) ->
// bit-identical outputs (index exactness mandatory).
__global__ __launch_bounds__(NTHR, 1)
void router_fused(const float* __restrict__ X, const float* __restrict__ Wt,
                  float* __restrict__ logits,
                  float* __restrict__ wout, float* __restrict__ eout) {
    extern __shared__ float smem[];            // 2 * BUFSZ floats = 192 KB

    const int tid  = threadIdx.x;
    const int w    = tid >> 5;
    const int lane = tid & 31;
    const int e0   = (w & 3) * 16;
    const int m1   = (w >> 2) * 64 + lane;
    const int m2   = m1 + 32;
    const int m0   = blockIdx.x * BM;

    const uint32_t smem_u32 = (uint32_t)__cvta_generic_to_shared(smem);

    float2 acc[2][8];
    #pragma unroll
    for (int r = 0; r < 2; r++)
        #pragma unroll
        for (int j = 0; j < 8; j++) acc[r][j] = make_float2(0.f, 0.f);

    // a-tile staging: float4 index f = tid + n*256 (n = 0..15):
    //   m-row = w + 8n  (same for all lanes of a warp -> coalesced LDG),
    //   q     = lane    (k-quad), k = 4q + j.
    // STS target: a_sm[k*BM + (m ^ (k>>2))] = a_sm[(4q+j)*BM + (m ^ q)].
    float4 pa[4];

    // ---- preload tile 0 ----
    {
        uint32_t b0 = smem_u32 + (uint32_t)(BK * BM) * 4u;
        #pragma unroll
        for (int i = 0; i < 8; i++)
            cp_async16(b0 + (tid + i * NTHR) * 16u, &Wt[(size_t)(tid + i * NTHR) * 4]);
        cp_async_commit();
        #pragma unroll
        for (int n = 0; n < 16; n++) {
            int m = w + 8 * n;
            float4 v = *reinterpret_cast<const float4*>(
                &X[(size_t)(m0 + m) * K_DIM + lane * 4]);
            int col = m ^ lane;
            float vs[4] = {v.x, v.y, v.z, v.w};
            #pragma unroll
            for (int j = 0; j < 4; j++)
                smem[(4 * lane + j) * BM + col] = vs[j];
        }
        cp_async_wait0();
    }
    __syncthreads();

    for (int t = 0; t < NTILE; t++) {
        const int cur = t & 1;
        const float* a_base = smem + cur * BUFSZ;
        const float* b_base = a_base + BK * BM;
        float* a_nx = smem + (cur ^ 1) * BUFSZ;

        const bool has_next = (t + 1 < NTILE);
        const int kn = (t + 1) * BK;

        // issue next-tile b (cp.async) + a batch 0 (coalesced LDG)
        if (has_next) {
            uint32_t bdst = smem_u32 + (uint32_t)((cur ^ 1) * BUFSZ + BK * BM) * 4u;
            const float* bsrc = &Wt[(size_t)kn * E_DIM];
            #pragma unroll
            for (int i = 0; i < 8; i++)
                cp_async16(bdst + (tid + i * NTHR) * 16u, bsrc + (size_t)(tid + i * NTHR) * 4);
            cp_async_commit();
            #pragma unroll
            for (int i = 0; i < 4; i++) {
                int m = w + 8 * i;
                pa[i] = *reinterpret_cast<const float4*>(
                    &X[(size_t)(m0 + m) * K_DIM + kn + lane * 4]);
            }
        }

        // ---- 4 quarters of 32 kk each (inner fully unrolled) ----
        #pragma unroll 1
        for (int qt = 0; qt < 4; qt++) {
            const float* a_sm = a_base + qt * 32 * BM;
            const float* b_sm = b_base + qt * 32 * E_DIM;
            const int m1q = m1 ^ (8 * qt);     // kk>>2 = 8qt | (u>>2), bits disjoint
            const int m2q = m2 ^ (8 * qt);

            #pragma unroll
            for (int u = 0; u < 32; u++) {
                const int c = u >> 2;
                float4 b4[4];
                #pragma unroll
                for (int j = 0; j < 4; j++)
                    b4[j] = *reinterpret_cast<const float4*>(&b_sm[u * E_DIM + e0 + 4 * j]);
                float a1 = a_sm[u * BM + (m1q ^ c)];
                float a2 = a_sm[u * BM + (m2q ^ c)];
                float2 ap1 = make_float2(a1, a1);
                float2 ap2 = make_float2(a2, a2);
                #pragma unroll
                for (int j = 0; j < 4; j++) {
                    float2 blo = make_float2(b4[j].x, b4[j].y);
                    float2 bhi = make_float2(b4[j].z, b4[j].w);
                    acc[0][2 * j]     = ffma2(ap1, blo, acc[0][2 * j]);
                    acc[0][2 * j + 1] = ffma2(ap1, bhi, acc[0][2 * j + 1]);
                    acc[1][2 * j]     = ffma2(ap2, blo, acc[1][2 * j]);
                    acc[1][2 * j + 1] = ffma2(ap2, bhi, acc[1][2 * j + 1]);
                }
            }

            // stage a batch qt into next buffer, issue batch qt+1
            if (has_next) {
                #pragma unroll
                for (int i = 0; i < 4; i++) {
                    int n = 4 * qt + i;
                    int m = w + 8 * n;
                    int col = m ^ lane;
                    float vs[4] = {pa[i].x, pa[i].y, pa[i].z, pa[i].w};
                    #pragma unroll
                    for (int j = 0; j < 4; j++)
                        a_nx[(4 * lane + j) * BM + col] = vs[j];
                }
                if (qt < 3) {
                    #pragma unroll
                    for (int i = 0; i < 4; i++) {
                        int m = w + 8 * (4 * (qt + 1) + i);
                        pa[i] = *reinterpret_cast<const float4*>(
                            &X[(size_t)(m0 + m) * K_DIM + kn + lane * 4]);
                    }
                }
            }
        }

        if (has_next) cp_async_wait0();
        __syncthreads();
    }

    // ---- epilogue: logits to global + stage rows in smem for topk ----
    #pragma unroll
    for (int r = 0; r < 2; r++) {
        int m = r ? m2 : m1;
        #pragma unroll
        for (int j = 0; j < 4; j++) {
            float4 v = make_float4(acc[r][2 * j].x, acc[r][2 * j].y,
                                   acc[r][2 * j + 1].x, acc[r][2 * j + 1].y);
            *reinterpret_cast<float4*>(&logits[(size_t)(m0 + m) * E_DIM + e0 + 4 * j]) = v;
            *reinterpret_cast<float4*>(&smem[m * LSTR + e0 + 4 * j]) = v;
        }
    }
    __syncthreads();

    // ---- top-8 + softmax: one thread per token (threads 0..127) ----
    if (tid < BM) {
        const float* row = &smem[tid * LSTR];
        float tv[TOPK];
        int   ti[TOPK];
        #pragma unroll
        for (int i = 0; i < TOPK; i++) { tv[i] = -3.4e38f; ti[i] = 0; }

        #pragma unroll
        for (int q = 0; q < E_DIM / 4; q++) {
            float4 v4 = *reinterpret_cast<const float4*>(&row[q * 4]);
            float vs[4] = {v4.x, v4.y, v4.z, v4.w};
            #pragma unroll
            for (int u = 0; u < 4; u++) {
                float v = vs[u];
                int   e = q * 4 + u;
                if (v > tv[TOPK - 1]) {
                    tv[TOPK - 1] = v; ti[TOPK - 1] = e;
                    #pragma unroll
                    for (int j = TOPK - 1; j > 0; j--) {
                        if (tv[j] > tv[j - 1]) {   // strict: ties keep earlier index
                            float tf = tv[j]; tv[j] = tv[j - 1]; tv[j - 1] = tf;
                            int   tx = ti[j]; ti[j] = ti[j - 1]; ti[j - 1] = tx;
                        }
                    }
                }
            }
        }

        float mx = tv[0];
        float ev[TOPK], ssum = 0.f;
        #pragma unroll
        for (int i = 0; i < TOPK; i++) { ev[i] = __expf(tv[i] - mx); ssum += ev[i]; }
        float inv = 1.f / ssum;
        size_t tok = (size_t)(m0 + tid);
        #pragma unroll
        for (int i = 0; i < TOPK; i++) {
            wout[tok * TOPK + i] = ev[i] * inv;
            eout[tok * TOPK + i] = (float)ti[i];
        }
    }
}

extern "C" void kernel_launch(void* const* d_in, const int* in_sizes, int n_in,
                              void* d_out, int out_size) {
    const float* X = (const float*)d_in[0];   // [4,4096,2048] fp32
    const float* W = (const float*)d_in[1];   // [64,2048]     fp32

    float* out    = (float*)d_out;
    float* logits = out;                                   // 16384*64
    float* wts    = out + (size_t)M_TOTAL * E_DIM;         // 16384*8
    float* exps   = wts + (size_t)M_TOTAL * TOPK;          // 16384*8

    float* Wt;
    cudaGetSymbolAddress((void**)&Wt, Wt_g);

    const int smem_bytes = 2 * BUFSZ * (int)sizeof(float);   // 196608 B
    cudaFuncSetAttribute(router_fused, cudaFuncAttributeMaxDynamicSharedMemorySize,
                         smem_bytes);

    transpose_w<<<(K_DIM * E_DIM) / 256, 256>>>(W, Wt);
    router_fused<<<M_TOTAL / BM, NTHR, smem_bytes>>>(X, Wt, logits, wts, exps);
}

// round 14
// speedup vs baseline: 1.3332x; 1.0503x over previous
#include <cuda_runtime.h>
#include <cstdint>

#define M_TOTAL 16384
#define K_DIM   2048
#define E_DIM   64
#define TOPK    8

#define BM    128
#define BK    64
#define NTILE (K_DIM / BK)   // 32
#define NTHR  256
#define LSTR  68             // epilogue logits row stride (floats)
#define BUFSZ (BK * BM + BK * E_DIM)   // 12288 floats per buffer (48 KB)

// One-time W transpose scratch: Wt[k][e]
__device__ float Wt_g[(size_t)K_DIM * E_DIM];

__global__ void transpose_w(const float* __restrict__ W, float* __restrict__ Wt) {
    int t = blockIdx.x * blockDim.x + threadIdx.x;   // 131072
    int e = t >> 11;
    int k = t & (K_DIM - 1);
    Wt[(size_t)k * E_DIM + e] = W[(size_t)e * K_DIM + k];
}

// Packed fp32x2 FMA; per-lane rounding identical to scalar fmaf.
__device__ __forceinline__ float2 ffma2(float2 a, float2 b, float2 c) {
    float2 d;
    asm("fma.rn.f32x2 %0, %1, %2, %3;"
        : "=l"(reinterpret_cast<unsigned long long&>(d))
        : "l"(reinterpret_cast<unsigned long long&>(a)),
          "l"(reinterpret_cast<unsigned long long&>(b)),
          "l"(reinterpret_cast<unsigned long long&>(c)));
    return d;
}

__device__ __forceinline__ void cp_async16(uint32_t dst_smem, const void* src) {
    asm volatile("cp.async.ca.shared.global [%0], [%1], 16;"
                 :: "r"(dst_smem), "l"(src));
}
__device__ __forceinline__ void cp_async_commit() {
    asm volatile("cp.async.commit_group;");
}
__device__ __forceinline__ void cp_async_wait0() {
    asm volatile("cp.async.wait_group 0;");
}

// Fused logits GEMM + top-8 + softmax. Round-11 structure (best measured:
// BK=64, 32 tiles, 96 KB double buffer, warp = 16 experts x 2 m-rows,
// uniform LDS.128 b, coalesced LDS.32 a, coalesced a-LDG) with the swizzle
// changed 4*(k>>2) -> 2*(k>>2): staging STS now FULLY conflict-free
// (round 11 had 2-way conflicts on every staging store).
// Sequential ascending-k FMA chain per (m,e) -> bit-identical outputs.
__global__ __launch_bounds__(NTHR, 1)
void router_fused(const float* __restrict__ X, const float* __restrict__ Wt,
                  float* __restrict__ logits,
                  float* __restrict__ wout, float* __restrict__ eout) {
    extern __shared__ float smem[];            // 2 * BUFSZ floats = 96 KB

    const int tid  = threadIdx.x;
    const int w    = tid >> 5;
    const int lane = tid & 31;
    const int e0   = (w & 3) * 16;
    const int m1   = (w >> 2) * 64 + lane;
    const int m2   = m1 + 32;
    const int m0   = blockIdx.x * BM;

    const uint32_t smem_u32 = (uint32_t)__cvta_generic_to_shared(smem);

    float2 acc[2][8];
    #pragma unroll
    for (int r = 0; r < 2; r++)
        #pragma unroll
        for (int j = 0; j < 8; j++) acc[r][j] = make_float2(0.f, 0.f);

    // a-tile: 128 rows x 64 k = 2048 float4 -> 8 per thread, in 2 batches of 4.
    // float4 index f = tid + i*256: row = f>>4 (16 float4 per row), q = f&15.
    int arow[8], aq[8];
    #pragma unroll
    for (int i = 0; i < 8; i++) { int f = tid + i * NTHR; arow[i] = f >> 4; aq[i] = f & 15; }

    // ---- preload tile 0 ----
    {
        // b tile: 64x64 floats = 1024 float4 -> 4 cp.async per thread
        uint32_t b0 = smem_u32 + (uint32_t)(BK * BM) * 4u;
        #pragma unroll
        for (int i = 0; i < 4; i++)
            cp_async16(b0 + (tid + i * NTHR) * 16u, &Wt[(size_t)(tid + i * NTHR) * 4]);
        cp_async_commit();
        // a tile: LDG -> swizzled STS (conflict-free: col = m ^ 2q)
        #pragma unroll
        for (int i = 0; i < 8; i++) {
            float4 v = *reinterpret_cast<const float4*>(
                &X[(size_t)(m0 + arow[i]) * K_DIM + aq[i] * 4]);
            int q = aq[i], col0 = arow[i] ^ (2 * q);
            float vs[4] = {v.x, v.y, v.z, v.w};
            #pragma unroll
            for (int j = 0; j < 4; j++)
                smem[(4 * q + j) * BM + col0] = vs[j];
        }
        cp_async_wait0();
    }
    __syncthreads();

    for (int t = 0; t < NTILE; t++) {
        const int cur = t & 1;
        const float* a_sm = smem + cur * BUFSZ;
        const float* b_sm = a_sm + BK * BM;
        float* a_nx = smem + (cur ^ 1) * BUFSZ;

        const bool has_next = (t + 1 < NTILE);
        float4 pa[4];

        // issue next-tile b (cp.async) + first a batch (LDG)
        if (has_next) {
            int kn = (t + 1) * BK;
            uint32_t bdst = smem_u32 + (uint32_t)((cur ^ 1) * BUFSZ + BK * BM) * 4u;
            const float* bsrc = &Wt[(size_t)kn * E_DIM];
            #pragma unroll
            for (int i = 0; i < 4; i++)
                cp_async16(bdst + (tid + i * NTHR) * 16u, bsrc + (size_t)(tid + i * NTHR) * 4);
            cp_async_commit();
            #pragma unroll
            for (int i = 0; i < 4; i++)
                pa[i] = *reinterpret_cast<const float4*>(
                    &X[(size_t)(m0 + arow[i]) * K_DIM + kn + aq[i] * 4]);
        }

        // ---- first half of mainloop ----
        #pragma unroll
        for (int kk = 0; kk < BK / 2; kk++) {
            const int sw = 2 * (kk >> 2);
            float4 b4[4];
            #pragma unroll
            for (int j = 0; j < 4; j++)
                b4[j] = *reinterpret_cast<const float4*>(&b_sm[kk * E_DIM + e0 + 4 * j]);
            float a1 = a_sm[kk * BM + (m1 ^ sw)];
            float a2 = a_sm[kk * BM + (m2 ^ sw)];
            float2 ap1 = make_float2(a1, a1);
            float2 ap2 = make_float2(a2, a2);
            #pragma unroll
            for (int j = 0; j < 4; j++) {
                float2 blo = make_float2(b4[j].x, b4[j].y);
                float2 bhi = make_float2(b4[j].z, b4[j].w);
                acc[0][2 * j]     = ffma2(ap1, blo, acc[0][2 * j]);
                acc[0][2 * j + 1] = ffma2(ap1, bhi, acc[0][2 * j + 1]);
                acc[1][2 * j]     = ffma2(ap2, blo, acc[1][2 * j]);
                acc[1][2 * j + 1] = ffma2(ap2, bhi, acc[1][2 * j + 1]);
            }
        }

        // store a batch 1, issue a batch 2
        if (has_next) {
            int kn = (t + 1) * BK;
            #pragma unroll
            for (int i = 0; i < 4; i++) {
                int q = aq[i], col0 = arow[i] ^ (2 * q);
                float vs[4] = {pa[i].x, pa[i].y, pa[i].z, pa[i].w};
                #pragma unroll
                for (int j = 0; j < 4; j++)
                    a_nx[(4 * q + j) * BM + col0] = vs[j];
            }
            #pragma unroll
            for (int i = 0; i < 4; i++)
                pa[i] = *reinterpret_cast<const float4*>(
                    &X[(size_t)(m0 + arow[i + 4]) * K_DIM + kn + aq[i + 4] * 4]);
        }

        // ---- second half of mainloop ----
        #pragma unroll
        for (int kk = BK / 2; kk < BK; kk++) {
            const int sw = 2 * (kk >> 2);
            float4 b4[4];
            #pragma unroll
            for (int j = 0; j < 4; j++)
                b4[j] = *reinterpret_cast<const float4*>(&b_sm[kk * E_DIM + e0 + 4 * j]);
            float a1 = a_sm[kk * BM + (m1 ^ sw)];
            float a2 = a_sm[kk * BM + (m2 ^ sw)];
            float2 ap1 = make_float2(a1, a1);
            float2 ap2 = make_float2(a2, a2);
            #pragma unroll
            for (int j = 0; j < 4; j++) {
                float2 blo = make_float2(b4[j].x, b4[j].y);
                float2 bhi = make_float2(b4[j].z, b4[j].w);
                acc[0][2 * j]     = ffma2(ap1, blo, acc[0][2 * j]);
                acc[0][2 * j + 1] = ffma2(ap1, bhi, acc[0][2 * j + 1]);
                acc[1][2 * j]     = ffma2(ap2, blo, acc[1][2 * j]);
                acc[1][2 * j + 1] = ffma2(ap2, bhi, acc[1][2 * j + 1]);
            }
        }

        // store a batch 2, wait for b
        if (has_next) {
            #pragma unroll
            for (int i = 0; i < 4; i++) {
                int q = aq[i + 4], col0 = arow[i + 4] ^ (2 * q);
                float vs[4] = {pa[i].x, pa[i].y, pa[i].z, pa[i].w};
                #pragma unroll
                for (int j = 0; j < 4; j++)
                    a_nx[(4 * q + j) * BM + col0] = vs[j];
            }
            cp_async_wait0();
        }
        __syncthreads();
    }

    // ---- epilogue: logits to global + stage rows in smem for topk ----
    #pragma unroll
    for (int r = 0; r < 2; r++) {
        int m = r ? m2 : m1;
        #pragma unroll
        for (int j = 0; j < 4; j++) {
            float4 v = make_float4(acc[r][2 * j].x, acc[r][2 * j].y,
                                   acc[r][2 * j + 1].x, acc[r][2 * j + 1].y);
            *reinterpret_cast<float4*>(&logits[(size_t)(m0 + m) * E_DIM + e0 + 4 * j]) = v;
            *reinterpret_cast<float4*>(&smem[m * LSTR + e0 + 4 * j]) = v;
        }
    }
    __syncthreads();

    // ---- top-8 + softmax: one thread per token (threads 0..127) ----
    if (tid < BM) {
        const float* row = &smem[tid * LSTR];
        float tv[TOPK];
        int   ti[TOPK];
        #pragma unroll
        for (int i = 0; i < TOPK; i++) { tv[i] = -3.4e38f; ti[i] = 0; }

        #pragma unroll
        for (int q = 0; q < E_DIM / 4; q++) {
            float4 v4 = *reinterpret_cast<const float4*>(&row[q * 4]);
            float vs[4] = {v4.x, v4.y, v4.z, v4.w};
            #pragma unroll
            for (int u = 0; u < 4; u++) {
                float v = vs[u];
                int   e = q * 4 + u;
                if (v > tv[TOPK - 1]) {
                    tv[TOPK - 1] = v; ti[TOPK - 1] = e;
                    #pragma unroll
                    for (int j = TOPK - 1; j > 0; j--) {
                        if (tv[j] > tv[j - 1]) {   // strict: ties keep earlier index
                            float tf = tv[j]; tv[j] = tv[j - 1]; tv[j - 1] = tf;
                            int   tx = ti[j]; ti[j] = ti[j - 1]; ti[j - 1] = tx;
                        }
                    }
                }
            }
        }

        float mx = tv[0];
        float ev[TOPK], ssum = 0.f;
        #pragma unroll
        for (int i = 0; i < TOPK; i++) { ev[i] = __expf(tv[i] - mx); ssum += ev[i]; }
        float inv = 1.f / ssum;
        size_t tok = (size_t)(m0 + tid);
        #pragma unroll
        for (int i = 0; i < TOPK; i++) {
            wout[tok * TOPK + i] = ev[i] * inv;
            eout[tok * TOPK + i] = (float)ti[i];
        }
    }
}

extern "C" void kernel_launch(void* const* d_in, const int* in_sizes, int n_in,
                              void* d_out, int out_size) {
    const float* X = (const float*)d_in[0];   // [4,4096,2048] fp32
    const float* W = (const float*)d_in[1];   // [64,2048]     fp32

    float* out    = (float*)d_out;
    float* logits = out;                                   // 16384*64
    float* wts    = out + (size_t)M_TOTAL * E_DIM;         // 16384*8
    float* exps   = wts + (size_t)M_TOTAL * TOPK;          // 16384*8

    float* Wt;
    cudaGetSymbolAddress((void**)&Wt, Wt_g);

    const int smem_bytes = 2 * BUFSZ * (int)sizeof(float);   // 98304 B
    cudaFuncSetAttribute(router_fused, cudaFuncAttributeMaxDynamicSharedMemorySize,
                         smem_bytes);

    transpose_w<<<(K_DIM * E_DIM) / 256, 256>>>(W, Wt);
    router_fused<<<M_TOTAL / BM, NTHR, smem_bytes>>>(X, Wt, logits, wts, exps);
}

// round 15
// speedup vs baseline: 1.3574x; 1.0181x over previous
#include <cuda_runtime.h>
#include <cstdint>

#define M_TOTAL 16384
#define K_DIM   2048
#define E_DIM   64
#define TOPK    8

#define BM    128
#define BK    64
#define NTILE (K_DIM / BK)   // 32
#define NTHR  256
#define ASTR  68             // a_sm row stride (floats): 64 data + 4 pad; 16B-aligned,
                             // STS.128 / LDS.128 both conflict-free (banks 4m+4q)
#define BUFSZ (BM * ASTR + BK * E_DIM)   // 12800 floats per buffer (51.2 KB)

// One-time W transpose scratch: Wt[k][e]
__device__ float Wt_g[(size_t)K_DIM * E_DIM];

__global__ void transpose_w(const float* __restrict__ W, float* __restrict__ Wt) {
    int t = blockIdx.x * blockDim.x + threadIdx.x;   // 131072
    int e = t >> 11;
    int k = t & (K_DIM - 1);
    Wt[(size_t)k * E_DIM + e] = W[(size_t)e * K_DIM + k];
}

// Packed fp32x2 FMA; per-lane rounding identical to scalar fmaf.
__device__ __forceinline__ float2 ffma2(float2 a, float2 b, float2 c) {
    float2 d;
    asm("fma.rn.f32x2 %0, %1, %2, %3;"
        : "=l"(reinterpret_cast<unsigned long long&>(d))
        : "l"(reinterpret_cast<unsigned long long&>(a)),
          "l"(reinterpret_cast<unsigned long long&>(b)),
          "l"(reinterpret_cast<unsigned long long&>(c)));
    return d;
}

__device__ __forceinline__ void cp_async16(uint32_t dst_smem, const void* src) {
    asm volatile("cp.async.ca.shared.global [%0], [%1], 16;"
                 :: "r"(dst_smem), "l"(src));
}
__device__ __forceinline__ void cp_async_commit() {
    asm volatile("cp.async.commit_group;");
}
__device__ __forceinline__ void cp_async_wait0() {
    asm volatile("cp.async.wait_group 0;");
}

// Fused logits GEMM + top-8 + softmax. Round-14 structure with the a-tile
// kept M-MAJOR (stride 68): staging is 4 STS.128/thread/tile (no transpose,
// no swizzle ALU; was 32 STS.32), mainloop reads a via one LDS.128 per
// 4 k-steps per m-row. b unchanged (k-major, uniform LDS.128, cp.async).
// Sequential ascending-k FMA chain per (m,e) -> bit-identical outputs
// (index exactness is mandatory; tensor formats are off the table).
__global__ __launch_bounds__(NTHR, 1)
void router_fused(const float* __restrict__ X, const float* __restrict__ Wt,
                  float* __restrict__ logits,
                  float* __restrict__ wout, float* __restrict__ eout) {
    extern __shared__ float smem[];            // 2 * BUFSZ floats = 102.4 KB

    const int tid  = threadIdx.x;
    const int w    = tid >> 5;
    const int lane = tid & 31;
    const int e0   = (w & 3) * 16;
    const int m1   = (w >> 2) * 64 + lane;
    const int m2   = m1 + 32;
    const int m0   = blockIdx.x * BM;

    const uint32_t smem_u32 = (uint32_t)__cvta_generic_to_shared(smem);

    float2 acc[2][8];
    #pragma unroll
    for (int r = 0; r < 2; r++)
        #pragma unroll
        for (int j = 0; j < 8; j++) acc[r][j] = make_float2(0.f, 0.f);

    // a-tile: 128 rows x 16 float4 = 2048 float4 -> 8 per thread (2 batches).
    // f = tid + i*256: row = f>>4, q = f&15. LDG coalesced (half-warp per row).
    int arow[8], aq[8];
    #pragma unroll
    for (int i = 0; i < 8; i++) { int f = tid + i * NTHR; arow[i] = f >> 4; aq[i] = f & 15; }

    // ---- preload tile 0 ----
    {
        uint32_t b0 = smem_u32 + (uint32_t)(BM * ASTR) * 4u;
        #pragma unroll
        for (int i = 0; i < 4; i++)
            cp_async16(b0 + (tid + i * NTHR) * 16u, &Wt[(size_t)(tid + i * NTHR) * 4]);
        cp_async_commit();
        #pragma unroll
        for (int i = 0; i < 8; i++) {
            float4 v = *reinterpret_cast<const float4*>(
                &X[(size_t)(m0 + arow[i]) * K_DIM + aq[i] * 4]);
            *reinterpret_cast<float4*>(&smem[arow[i] * ASTR + aq[i] * 4]) = v;
        }
        cp_async_wait0();
    }
    __syncthreads();

    for (int t = 0; t < NTILE; t++) {
        const int cur = t & 1;
        const float* a_sm = smem + cur * BUFSZ;
        const float* b_sm = a_sm + BM * ASTR;
        float* a_nx = smem + (cur ^ 1) * BUFSZ;

        const bool has_next = (t + 1 < NTILE);
        float4 pa[4];

        // issue next-tile b (cp.async) + first a batch (LDG)
        if (has_next) {
            int kn = (t + 1) * BK;
            uint32_t bdst = smem_u32 + (uint32_t)((cur ^ 1) * BUFSZ + BM * ASTR) * 4u;
            const float* bsrc = &Wt[(size_t)kn * E_DIM];
            #pragma unroll
            for (int i = 0; i < 4; i++)
                cp_async16(bdst + (tid + i * NTHR) * 16u, bsrc + (size_t)(tid + i * NTHR) * 4);
            cp_async_commit();
            #pragma unroll
            for (int i = 0; i < 4; i++)
                pa[i] = *reinterpret_cast<const float4*>(
                    &X[(size_t)(m0 + arow[i]) * K_DIM + kn + aq[i] * 4]);
        }

        // ---- first half: k-quads 0..7 ----
        #pragma unroll
        for (int kq = 0; kq < 8; kq++) {
            float4 a1v = *reinterpret_cast<const float4*>(&a_sm[m1 * ASTR + kq * 4]);
            float4 a2v = *reinterpret_cast<const float4*>(&a_sm[m2 * ASTR + kq * 4]);
            float a1s[4] = {a1v.x, a1v.y, a1v.z, a1v.w};
            float a2s[4] = {a2v.x, a2v.y, a2v.z, a2v.w};
            #pragma unroll
            for (int u = 0; u < 4; u++) {
                const int kk = kq * 4 + u;
                float4 b4[4];
                #pragma unroll
                for (int j = 0; j < 4; j++)
                    b4[j] = *reinterpret_cast<const float4*>(&b_sm[kk * E_DIM + e0 + 4 * j]);
                float2 ap1 = make_float2(a1s[u], a1s[u]);
                float2 ap2 = make_float2(a2s[u], a2s[u]);
                #pragma unroll
                for (int j = 0; j < 4; j++) {
                    float2 blo = make_float2(b4[j].x, b4[j].y);
                    float2 bhi = make_float2(b4[j].z, b4[j].w);
                    acc[0][2 * j]     = ffma2(ap1, blo, acc[0][2 * j]);
                    acc[0][2 * j + 1] = ffma2(ap1, bhi, acc[0][2 * j + 1]);
                    acc[1][2 * j]     = ffma2(ap2, blo, acc[1][2 * j]);
                    acc[1][2 * j + 1] = ffma2(ap2, bhi, acc[1][2 * j + 1]);
                }
            }
        }

        // stage a batch 1 (4 STS.128), issue a batch 2
        if (has_next) {
            int kn = (t + 1) * BK;
            #pragma unroll
            for (int i = 0; i < 4; i++)
                *reinterpret_cast<float4*>(&a_nx[arow[i] * ASTR + aq[i] * 4]) = pa[i];
            #pragma unroll
            for (int i = 0; i < 4; i++)
                pa[i] = *reinterpret_cast<const float4*>(
                    &X[(size_t)(m0 + arow[i + 4]) * K_DIM + kn + aq[i + 4] * 4]);
        }

        // ---- second half: k-quads 8..15 ----
        #pragma unroll
        for (int kq = 8; kq < 16; kq++) {
            float4 a1v = *reinterpret_cast<const float4*>(&a_sm[m1 * ASTR + kq * 4]);
            float4 a2v = *reinterpret_cast<const float4*>(&a_sm[m2 * ASTR + kq * 4]);
            float a1s[4] = {a1v.x, a1v.y, a1v.z, a1v.w};
            float a2s[4] = {a2v.x, a2v.y, a2v.z, a2v.w};
            #pragma unroll
            for (int u = 0; u < 4; u++) {
                const int kk = kq * 4 + u;
                float4 b4[4];
                #pragma unroll
                for (int j = 0; j < 4; j++)
                    b4[j] = *reinterpret_cast<const float4*>(&b_sm[kk * E_DIM + e0 + 4 * j]);
                float2 ap1 = make_float2(a1s[u], a1s[u]);
                float2 ap2 = make_float2(a2s[u], a2s[u]);
                #pragma unroll
                for (int j = 0; j < 4; j++) {
                    float2 blo = make_float2(b4[j].x, b4[j].y);
                    float2 bhi = make_float2(b4[j].z, b4[j].w);
                    acc[0][2 * j]     = ffma2(ap1, blo, acc[0][2 * j]);
                    acc[0][2 * j + 1] = ffma2(ap1, bhi, acc[0][2 * j + 1]);
                    acc[1][2 * j]     = ffma2(ap2, blo, acc[1][2 * j]);
                    acc[1][2 * j + 1] = ffma2(ap2, bhi, acc[1][2 * j + 1]);
                }
            }
        }

        // stage a batch 2, wait for b
        if (has_next) {
            #pragma unroll
            for (int i = 0; i < 4; i++)
                *reinterpret_cast<float4*>(&a_nx[arow[i + 4] * ASTR + aq[i + 4] * 4]) = pa[i];
            cp_async_wait0();
        }
        __syncthreads();
    }

    // ---- epilogue: logits to global + stage rows in smem for topk ----
    #pragma unroll
    for (int r = 0; r < 2; r++) {
        int m = r ? m2 : m1;
        #pragma unroll
        for (int j = 0; j < 4; j++) {
            float4 v = make_float4(acc[r][2 * j].x, acc[r][2 * j].y,
                                   acc[r][2 * j + 1].x, acc[r][2 * j + 1].y);
            *reinterpret_cast<float4*>(&logits[(size_t)(m0 + m) * E_DIM + e0 + 4 * j]) = v;
            *reinterpret_cast<float4*>(&smem[m * ASTR + e0 + 4 * j]) = v;
        }
    }
    __syncthreads();

    // ---- top-8 + softmax: one thread per token (threads 0..127) ----
    if (tid < BM) {
        const float* row = &smem[tid * ASTR];
        float tv[TOPK];
        int   ti[TOPK];
        #pragma unroll
        for (int i = 0; i < TOPK; i++) { tv[i] = -3.4e38f; ti[i] = 0; }

        #pragma unroll
        for (int q = 0; q < E_DIM / 4; q++) {
            float4 v4 = *reinterpret_cast<const float4*>(&row[q * 4]);
            float vs[4] = {v4.x, v4.y, v4.z, v4.w};
            #pragma unroll
            for (int u = 0; u < 4; u++) {
                float v = vs[u];
                int   e = q * 4 + u;
                if (v > tv[TOPK - 1]) {
                    tv[TOPK - 1] = v; ti[TOPK - 1] = e;
                    #pragma unroll
                    for (int j = TOPK - 1; j > 0; j--) {
                        if (tv[j] > tv[j - 1]) {   // strict: ties keep earlier index
                            float tf = tv[j]; tv[j] = tv[j - 1]; tv[j - 1] = tf;
                            int   tx = ti[j]; ti[j] = ti[j - 1]; ti[j - 1] = tx;
                        }
                    }
                }
            }
        }

        float mx = tv[0];
        float ev[TOPK], ssum = 0.f;
        #pragma unroll
        for (int i = 0; i < TOPK; i++) { ev[i] = __expf(tv[i] - mx); ssum += ev[i]; }
        float inv = 1.f / ssum;
        size_t tok = (size_t)(m0 + tid);
        #pragma unroll
        for (int i = 0; i < TOPK; i++) {
            wout[tok * TOPK + i] = ev[i] * inv;
            eout[tok * TOPK + i] = (float)ti[i];
        }
    }
}

extern "C" void kernel_launch(void* const* d_in, const int* in_sizes, int n_in,
                              void* d_out, int out_size) {
    const float* X = (const float*)d_in[0];   // [4,4096,2048] fp32
    const float* W = (const float*)d_in[1];   // [64,2048]     fp32

    float* out    = (float*)d_out;
    float* logits = out;                                   // 16384*64
    float* wts    = out + (size_t)M_TOTAL * E_DIM;         // 16384*8
    float* exps   = wts + (size_t)M_TOTAL * TOPK;          // 16384*8

    float* Wt;
    cudaGetSymbolAddress((void**)&Wt, Wt_g);

    const int smem_bytes = 2 * BUFSZ * (int)sizeof(float);   // 102400 B
    cudaFuncSetAttribute(router_fused, cudaFuncAttributeMaxDynamicSharedMemorySize,
                         smem_bytes);

    transpose_w<<<(K_DIM * E_DIM) / 256, 256>>>(W, Wt);
    router_fused<<<M_TOTAL / BM, NTHR, smem_bytes>>>(X, Wt, logits, wts, exps);
}